// round 7
// baseline (speedup 1.0000x reference)
#include <cuda_runtime.h>
#include <cstdint>

typedef unsigned long long u64;

#define B_  16
#define N_  8192
#define C_  256
#define K_  4096

// Output layout (float32): [features][indices][adjacency][scores]
#define OFF_FEAT   ((size_t)0)
#define OFF_IDX    ((size_t)B_ * K_ * C_)
#define OFF_ADJ    (OFF_IDX + (size_t)B_ * K_)
#define OFF_SCORES (OFF_ADJ + (size_t)B_ * K_ * K_)

// Scratch (device globals; no allocation allowed)
__device__ __align__(16) unsigned short g_idx[B_ * K_];
__device__ int g_pos[B_ * N_];
__device__ __align__(16) u64 g_keys[B_ * N_];      // 1 MB sort scratch
__device__ int g_bar0, g_bar1;
__device__ volatile int g_done;

// ---------------------------------------------------------------------------
// Bitonic convention: at stage (k, j), the lower element of a pair keeps the
// max iff (i & k)==0  => final order descending.  Composite key
// flipped_score<<16 | (8191-idx) breaks ties by ascending index (jax.lax.top_k).
// ---------------------------------------------------------------------------
__device__ __forceinline__ void ce_pair(u64 &lo, u64 &hi, bool desc) {
    u64 a = lo, b = hi;
    u64 mx = a > b ? a : b;
    u64 mn = a > b ? b : a;
    lo = desc ? mx : mn;
    hi = desc ? mn : mx;
}
__device__ __forceinline__ u64 shfl_ce(u64 v, int j, bool keepmax) {
    u64 o = __shfl_xor_sync(0xFFFFFFFFu, v, j);
    u64 mx = v > o ? v : o;
    u64 mn = v > o ? o : v;
    return keepmax ? mx : mn;
}
__device__ __forceinline__ void smem_ce(u64* s, int i, int m, bool desc) {
    u64 a = s[i], c = s[m];
    if ((a < c) == desc) { s[i] = c; s[m] = a; }
}

// 64-block barrier among sorter blocks (all wave-1 resident: lowest blockIdx).
__device__ __forceinline__ void sorter_barrier(int* ctr) {
    __threadfence();
    __syncthreads();
    if (threadIdx.x == 0) {
        atomicAdd(ctr, 1);
        volatile int* vp = ctr;
        while (*vp < 64) __nanosleep(64);
        __threadfence();
    }
    __syncthreads();
}

// ---------------------------------------------------------------------------
// Reset kernel: zero the cross-replay counters (device globals persist).
// ---------------------------------------------------------------------------
__global__ void reset_kernel() { g_bar0 = 0; g_bar1 = 0; g_done = 0; }

// ---------------------------------------------------------------------------
// Mega kernel.  Blocks [0,64): sort pipeline (phases A/B/C with internal
// barriers), then set g_done.  Blocks [64, 64+8192): adjacency gather (row
// load overlaps the sort; spin on g_done before the indexed phase).
// Blocks [64+8192, 64+16384): feature gather (spin exits ~instantly).
// ---------------------------------------------------------------------------
__global__ __launch_bounds__(512, 3)
void mega_kernel(const float* __restrict__ scores,
                 const float* __restrict__ A,
                 const float4* __restrict__ feat,
                 float* __restrict__ out_feat4,
                 float* __restrict__ out_idxf,
                 float* __restrict__ out_adj,
                 float* __restrict__ out_scores)
{
    __shared__ __align__(16) char smraw[32768];
    const int t = threadIdx.x;

    if (blockIdx.x < 64) {
        // =================== SORTER ===================
        u64* s = (u64*)smraw;
        const int sb = blockIdx.x;
        const int l  = t & 31;

        // ---- Phase A: sort one 2048-chunk (k=2..2048) ----
        {
            const int b  = sb >> 2;
            const int cb = (sb & 3) << 11;
            const int wb = (t >> 5) << 7;                // warp*128
            const float* sc = scores + (size_t)b * N_;

            u64 v[4];
            #pragma unroll
            for (int e = 0; e < 4; e++) {
                int I = cb + wb + e * 32 + l;
                unsigned u = __float_as_uint(sc[I]);
                u ^= (u & 0x80000000u) ? 0xFFFFFFFFu : 0x80000000u;
                v[e] = ((u64)u << 16) | (unsigned)(8191 - I);
                g_pos[b * N_ + cb + e * 512 + t] = -1;
            }

            #pragma unroll
            for (int k = 2; k <= 128; k <<= 1) {
                #pragma unroll
                for (int eb = 2; eb >= 1; eb >>= 1) {
                    const int j = eb << 5;
                    if (j < k) {
                        #pragma unroll
                        for (int e = 0; e < 4; e++)
                            if (!(e & eb)) {
                                bool desc = (((cb + wb + e * 32) & k) == 0);
                                ce_pair(v[e], v[e | eb], desc);
                            }
                    }
                }
                #pragma unroll
                for (int j = 16; j >= 1; j >>= 1) {
                    if (j < k) {
                        #pragma unroll
                        for (int e = 0; e < 4; e++) {
                            bool desc = (((cb + wb + e * 32 + l) & k) == 0);
                            v[e] = shfl_ce(v[e], j, desc == ((l & j) == 0));
                        }
                    }
                }
            }

            #pragma unroll 1
            for (int k = 256; k <= 2048; k <<= 1) {
                #pragma unroll
                for (int e = 0; e < 4; e++) s[wb + e * 32 + l] = v[e];
                __syncthreads();
                #pragma unroll 1
                for (int j = k >> 1; j >= 128; j >>= 1) {
                    #pragma unroll
                    for (int q = 0; q < 2; q++) {
                        int p = t + q * 512;
                        int i = ((p & ~(j - 1)) << 1) | (p & (j - 1));
                        bool desc = (((cb + i) & k) == 0);
                        smem_ce(s, i, i + j, desc);
                    }
                    __syncthreads();
                }
                #pragma unroll
                for (int e = 0; e < 4; e++) v[e] = s[wb + e * 32 + l];
                __syncthreads();
                #pragma unroll
                for (int eb = 2; eb >= 1; eb >>= 1) {
                    #pragma unroll
                    for (int e = 0; e < 4; e++)
                        if (!(e & eb)) {
                            bool desc = (((cb + wb + e * 32) & k) == 0);
                            ce_pair(v[e], v[e | eb], desc);
                        }
                }
                #pragma unroll
                for (int j = 16; j >= 1; j >>= 1) {
                    #pragma unroll
                    for (int e = 0; e < 4; e++) {
                        bool desc = (((cb + wb + e * 32 + l) & k) == 0);
                        v[e] = shfl_ce(v[e], j, desc == ((l & j) == 0));
                    }
                }
            }
            #pragma unroll
            for (int e = 0; e < 4; e++)
                g_keys[(size_t)b * N_ + cb + wb + e * 32 + l] = v[e];
        }
        sorter_barrier(&g_bar0);

        // ---- Phase B: k=4096 merge (blocks 0..31) ----
        if (sb < 32) {
            const int b    = sb >> 1;
            const int base = (sb & 1) << 12;
            const bool desc = ((base & 4096) == 0);
            const int wb = (t >> 5) << 8;                // warp*256
            u64* gk = g_keys + (size_t)b * N_ + base;

            for (int x = t; x < 4096; x += 512) s[x] = gk[x];
            __syncthreads();
            #pragma unroll 1
            for (int j = 2048; j >= 256; j >>= 1) {
                #pragma unroll
                for (int q = 0; q < 4; q++) {
                    int p = t + q * 512;
                    int i = ((p & ~(j - 1)) << 1) | (p & (j - 1));
                    smem_ce(s, i, i + j, desc);
                }
                __syncthreads();
            }
            u64 v[8];
            #pragma unroll
            for (int e = 0; e < 8; e++) v[e] = s[wb + e * 32 + l];
            #pragma unroll
            for (int eb = 4; eb >= 1; eb >>= 1)
                #pragma unroll
                for (int e = 0; e < 8; e++)
                    if (!(e & eb)) ce_pair(v[e], v[e | eb], desc);
            #pragma unroll
            for (int j = 16; j >= 1; j >>= 1)
                #pragma unroll
                for (int e = 0; e < 8; e++)
                    v[e] = shfl_ce(v[e], j, desc == ((l & j) == 0));
            #pragma unroll
            for (int e = 0; e < 8; e++) gk[wb + e * 32 + l] = v[e];
        }
        sorter_barrier(&g_bar1);

        // ---- Phase C: orbit j=4096..1024 + window finalize + emit ----
        {
            const int b = sb >> 2;
            const int w = sb & 3;
            const u64* gk = g_keys + (size_t)b * N_;

            #pragma unroll
            for (int h = 0; h < 2; h++) {
                int col = t + (h << 9);
                u64 v[8];
                #pragma unroll
                for (int m = 0; m < 8; m++) v[m] = gk[col + (m << 10)];
                #pragma unroll
                for (int m = 0; m < 4; m++) {
                    u64 a = v[m], c = v[m + 4];
                    v[m] = a > c ? a : c;                 // j=4096 keep-max
                }
                ce_pair(v[0], v[2], true);  ce_pair(v[1], v[3], true);  // j=2048
                ce_pair(v[0], v[1], true);  ce_pair(v[2], v[3], true);  // j=1024
                u64 keep = (w == 0) ? v[0] : (w == 1) ? v[1]
                         : (w == 2) ? v[2] : v[3];
                s[col] = keep;
            }
            __syncthreads();

            #pragma unroll
            for (int j = 512; j >= 32; j >>= 1) {
                int i = ((t & ~(j - 1)) << 1) | (t & (j - 1));
                smem_ce(s, i, i + j, true);
                __syncthreads();
            }

            const int wb = (t >> 5) << 6;                // warp*64
            u64 x0 = s[wb + l], x1 = s[wb + 32 + l];
            #pragma unroll
            for (int j = 16; j >= 1; j >>= 1) {
                x0 = shfl_ce(x0, j, (l & j) == 0);
                x1 = shfl_ce(x1, j, (l & j) == 0);
            }
            #pragma unroll
            for (int h = 0; h < 2; h++) {
                u64 x = h ? x1 : x0;
                int rank = (w << 10) + wb + h * 32 + l;
                int idx = 8191 - (int)(x & 0xFFFF);
                unsigned ku = (unsigned)(x >> 16);
                unsigned orig = (ku & 0x80000000u) ? (ku ^ 0x80000000u) : ~ku;
                g_idx[b * K_ + rank] = (unsigned short)idx;
                out_idxf[(size_t)b * K_ + rank]   = (float)idx;
                out_scores[(size_t)b * K_ + rank] = __uint_as_float(orig);
                g_pos[b * N_ + idx] = rank;
            }
        }
        __threadfence();
        __syncthreads();
        if (t == 0) atomicAdd((int*)&g_done, 1);
        return;
    }

    // =================== GATHER ===================
    int blk = blockIdx.x - 64;
    if (blk < 8192) {
        // adjacency: stage source row first (overlaps the sort), then spin
        float* row = (float*)smraw;
        const int r = blk;
        const float4* src  = (const float4*)(A + (size_t)r * N_);
        float4*       rowv = (float4*)row;
        for (int x = t; x < N_ / 4; x += 512)
            rowv[x] = __ldcs(src + x);

        if (t == 0) {
            while (g_done < 64) __nanosleep(128);
            __threadfence();
        }
        __syncthreads();   // covers row staging + flag acquire

        #pragma unroll 1
        for (int b = 0; b < B_; ++b) {
            int i = g_pos[b * N_ + r];
            if (i < 0) continue;
            float4* obase = (float4*)(out_adj + ((size_t)b * K_ + i) * K_);
            const ushort4* idx4 = (const ushort4*)(g_idx + b * K_);
            for (int x = t; x < K_ / 4; x += 512) {
                ushort4 c = idx4[x];
                __stcs(obase + x,
                       make_float4(row[c.x], row[c.y], row[c.z], row[c.w]));
            }
        }
    } else {
        if (t == 0) {
            while (g_done < 64) __nanosleep(128);
            __threadfence();
        }
        __syncthreads();

        int o = (blk - 8192) * 512 + t;                 // 0..4194303
        int frow = o >> 6;                               // C/4=64 f4/row
        int c    = o & 63;
        int b    = frow >> 12;                           // K rows/batch
        int rr   = g_idx[frow];
        __stcs(((float4*)out_feat4) + o,
               __ldcs(feat + ((size_t)(b << 13) + rr) * 64 + c));
    }
}

// ---------------------------------------------------------------------------
extern "C" void kernel_launch(void* const* d_in, const int* in_sizes, int n_in,
                              void* d_out, int out_size)
{
    const float* scores = (const float*)d_in[0];   // (B, N)
    const float* feat   = (const float*)d_in[1];   // (B, N, C)
    const float* adj    = (const float*)d_in[2];   // (N, N)
    float* out = (float*)d_out;

    float* out_feat   = out + OFF_FEAT;
    float* out_idxf   = out + OFF_IDX;
    float* out_adj    = out + OFF_ADJ;
    float* out_scores = out + OFF_SCORES;

    reset_kernel<<<1, 1>>>();
    mega_kernel<<<64 + 16384, 512>>>(scores, adj, (const float4*)feat,
                                     out_feat, out_idxf, out_adj, out_scores);
}

// round 10
// speedup vs baseline: 1.1843x; 1.1843x over previous
#include <cuda_runtime.h>
#include <cstdint>

typedef unsigned long long u64;

#define B_  16
#define N_  8192
#define C_  256
#define K_  4096

// Output layout (float32): [features][indices][adjacency][scores]
#define OFF_FEAT   ((size_t)0)
#define OFF_IDX    ((size_t)B_ * K_ * C_)
#define OFF_ADJ    (OFF_IDX + (size_t)B_ * K_)
#define OFF_SCORES (OFF_ADJ + (size_t)B_ * K_ * K_)

// Scratch (device globals; no allocation allowed)
__device__ __align__(16) unsigned short g_idx[B_ * K_];
__device__ int g_pos[B_ * N_];
__device__ __align__(16) u64 g_keys[B_ * N_];      // 1 MB sort scratch

// ---------------------------------------------------------------------------
// Bitonic convention (chunk-local): at stage (k, j), the lower element of a
// pair keeps the max iff (local_i & k)==0  => EVERY chunk independently
// sorted descending (required by the merge-path ranker).  Composite key
// flipped_score<<16 | (8191-idx) breaks ties by ascending index
// (jax.lax.top_k) and makes all keys unique => strict total order.
// ---------------------------------------------------------------------------
__device__ __forceinline__ void ce_pair(u64 &lo, u64 &hi, bool desc) {
    u64 a = lo, b = hi;
    u64 mx = a > b ? a : b;
    u64 mn = a > b ? b : a;
    lo = desc ? mx : mn;
    hi = desc ? mn : mx;
}
__device__ __forceinline__ u64 shfl_ce(u64 v, int j, bool keepmax) {
    u64 o = __shfl_xor_sync(0xFFFFFFFFu, v, j);
    u64 mx = v > o ? v : o;
    u64 mn = v > o ? o : v;
    return keepmax ? mx : mn;
}
__device__ __forceinline__ void smem_ce(u64* s, int i, int m, bool desc) {
    u64 a = s[i], c = s[m];
    if ((a < c) == desc) { s[i] = c; s[m] = a; }
}

// ---------------------------------------------------------------------------
// K1: sort each 2048-chunk fully DESCENDING (k=2..2048, chunk-local desc).
// grid B*4, block 512, 4 u64/thread, 16KB smem. Builds keys, clears g_pos.
// ---------------------------------------------------------------------------
__global__ __launch_bounds__(512)
void sort2048_kernel(const float* __restrict__ scores)
{
    __shared__ u64 s[2048];
    const int b  = blockIdx.x >> 2;
    const int cb = (blockIdx.x & 3) << 11;          // batch-local chunk base
    const int t  = threadIdx.x;
    const int l  = t & 31;
    const int wbase = (t >> 5) << 7;                // warp*128 (chunk-local)
    const float* sc = scores + (size_t)b * N_;

    u64 v[4];
    #pragma unroll
    for (int e = 0; e < 4; e++) {
        int I = cb + wbase + e * 32 + l;            // batch-local (for key)
        unsigned u = __float_as_uint(sc[I]);
        u ^= (u & 0x80000000u) ? 0xFFFFFFFFu : 0x80000000u;
        v[e] = ((u64)u << 16) | (unsigned)(8191 - I);
        g_pos[b * N_ + cb + e * 512 + t] = -1;
    }

    // ---- register phase: k = 2..128 (chunk-local indices only) ----
    #pragma unroll
    for (int k = 2; k <= 128; k <<= 1) {
        #pragma unroll
        for (int eb = 2; eb >= 1; eb >>= 1) {
            const int j = eb << 5;
            if (j < k) {
                #pragma unroll
                for (int e = 0; e < 4; e++)
                    if (!(e & eb)) {
                        bool desc = (((wbase + e * 32) & k) == 0);
                        ce_pair(v[e], v[e | eb], desc);
                    }
            }
        }
        #pragma unroll
        for (int j = 16; j >= 1; j >>= 1) {
            if (j < k) {
                #pragma unroll
                for (int e = 0; e < 4; e++) {
                    bool desc = (((wbase + e * 32 + l) & k) == 0);
                    v[e] = shfl_ce(v[e], j, desc == ((l & j) == 0));
                }
            }
        }
    }

    // ---- k = 256..2048: smem stages j>=128, register tail j<=64 ----
    #pragma unroll 1
    for (int k = 256; k <= 2048; k <<= 1) {
        #pragma unroll
        for (int e = 0; e < 4; e++) s[wbase + e * 32 + l] = v[e];
        __syncthreads();
        #pragma unroll 1
        for (int j = k >> 1; j >= 128; j >>= 1) {
            #pragma unroll
            for (int q = 0; q < 2; q++) {
                int p = t + q * 512;                       // 0..1023
                int i = ((p & ~(j - 1)) << 1) | (p & (j - 1));
                bool desc = ((i & k) == 0);                // chunk-local
                smem_ce(s, i, i + j, desc);
            }
            __syncthreads();
        }
        #pragma unroll
        for (int e = 0; e < 4; e++) v[e] = s[wbase + e * 32 + l];
        __syncthreads();
        #pragma unroll
        for (int eb = 2; eb >= 1; eb >>= 1) {
            #pragma unroll
            for (int e = 0; e < 4; e++)
                if (!(e & eb)) {
                    bool desc = (((wbase + e * 32) & k) == 0);
                    ce_pair(v[e], v[e | eb], desc);
                }
        }
        #pragma unroll
        for (int j = 16; j >= 1; j >>= 1) {
            #pragma unroll
            for (int e = 0; e < 4; e++) {
                bool desc = (((wbase + e * 32 + l) & k) == 0);
                v[e] = shfl_ce(v[e], j, desc == ((l & j) == 0));
            }
        }
    }

    #pragma unroll
    for (int e = 0; e < 4; e++)
        g_keys[(size_t)b * N_ + cb + wbase + e * 32 + l] = v[e];
}

// ---------------------------------------------------------------------------
// K2: merge-path rank + emit.  Each of the B*N elements computes its global
// descending rank = position-in-own-chunk + sum over the other 3 descending
// chunks of count(elements > x) via binary search (unique keys => exact).
// Elements with rank < K emit directly.  Invariant: a[0..lo) > x,
// a[hi..2048) <= x; terminates in <= 12 iterations.
// ---------------------------------------------------------------------------
__global__ __launch_bounds__(512)
void rank_emit_kernel(float* __restrict__ out_idxf,
                      float* __restrict__ out_scores)
{
    const int gid = blockIdx.x * 512 + threadIdx.x;    // 0 .. B*N-1
    const int b = gid >> 13;
    const int i = gid & (N_ - 1);
    const u64* keys = g_keys + (size_t)b * N_;
    const u64 x = keys[i];
    const int chunk = i >> 11;
    int rank = i & 2047;                               // greater elems in own chunk

    #pragma unroll
    for (int c = 0; c < 4; c++) {
        if (c == chunk) continue;
        const u64* a = keys + (c << 11);
        int lo = 0, hi = 2048;
        while (lo < hi) {                              // <= 12 iterations
            int mid = (lo + hi) >> 1;
            if (a[mid] > x) lo = mid + 1; else hi = mid;
        }
        rank += lo;                                    // # elements > x in chunk c
    }

    if (rank < K_) {
        int idx = 8191 - (int)(x & 0xFFFF);
        unsigned ku = (unsigned)(x >> 16);
        unsigned orig = (ku & 0x80000000u) ? (ku ^ 0x80000000u) : ~ku;
        g_idx[b * K_ + rank] = (unsigned short)idx;
        out_idxf[(size_t)b * K_ + rank]   = (float)idx;
        out_scores[(size_t)b * K_ + rank] = __uint_as_float(orig);
        g_pos[b * N_ + idx] = rank;
    }
}

// ---------------------------------------------------------------------------
// Combined gather (round-5 proven form): blocks [0,8192) stage one adjacency
// source row in SMEM and serve every batch containing it; blocks
// [8192,16384) gather features.  Streaming hints keep L2 for hot g_idx.
// ---------------------------------------------------------------------------
__global__ __launch_bounds__(512)
void gather_kernel(const float* __restrict__ A,
                   const float4* __restrict__ feat,
                   float* __restrict__ out_adj,
                   float4* __restrict__ out_feat)
{
    __shared__ float row[N_];   // 32 KB (adj branch only)
    if (blockIdx.x < 8192) {
        const int r = blockIdx.x;
        const float4* src  = (const float4*)(A + (size_t)r * N_);
        float4*       rowv = (float4*)row;
        for (int t = threadIdx.x; t < N_ / 4; t += 512)
            rowv[t] = __ldcs(src + t);
        __syncthreads();

        #pragma unroll 1
        for (int b = 0; b < B_; ++b) {
            int i = g_pos[b * N_ + r];
            if (i < 0) continue;
            float4* obase = (float4*)(out_adj + ((size_t)b * K_ + i) * K_);
            const ushort4* idx4 = (const ushort4*)(g_idx + b * K_);
            for (int t = threadIdx.x; t < K_ / 4; t += 512) {
                ushort4 c = idx4[t];
                __stcs(obase + t,
                       make_float4(row[c.x], row[c.y], row[c.z], row[c.w]));
            }
        }
    } else {
        int o = (blockIdx.x - 8192) * 512 + threadIdx.x;   // 0..4194303
        int frow = o >> 6;                                  // C/4=64 f4/row
        int c    = o & 63;
        int b    = frow >> 12;                              // K rows/batch
        int r    = g_idx[frow];
        __stcs(out_feat + o,
               __ldcs(feat + ((size_t)(b << 13) + r) * 64 + c));
    }
}

// ---------------------------------------------------------------------------
extern "C" void kernel_launch(void* const* d_in, const int* in_sizes, int n_in,
                              void* d_out, int out_size)
{
    const float* scores = (const float*)d_in[0];   // (B, N)
    const float* feat   = (const float*)d_in[1];   // (B, N, C)
    const float* adj    = (const float*)d_in[2];   // (N, N)
    float* out = (float*)d_out;

    float* out_feat   = out + OFF_FEAT;
    float* out_idxf   = out + OFF_IDX;
    float* out_adj    = out + OFF_ADJ;
    float* out_scores = out + OFF_SCORES;

    sort2048_kernel<<<B_ * 4, 512>>>(scores);
    rank_emit_kernel<<<B_ * N_ / 512, 512>>>(out_idxf, out_scores);

    gather_kernel<<<16384, 512>>>(adj, (const float4*)feat,
                                  out_adj, (float4*)out_feat);
}